// round 11
// baseline (speedup 1.0000x reference)
#include <cuda_runtime.h>
#include <cuda_fp16.h>

#define NN 100000
#define EE 1600000
#define CC 40
#define NBLK 98          // ceil(NN/1024)
#define LN_EPS 1e-5f

// packed fp32x2 FMA (PTX-only pattern; ptxas never emits it from C++)
#define FMA2(acc, a, b) \
    asm("fma.rn.f32x2 %0, %1, %2, %0;" : "+l"(acc) : "l"(a), "l"(b))

// ---------------- device scratch ----------------
// g_cnt: zero at process start; histscan builds degree; countdown scatter
// restores it to exactly 0 -> every graph replay sees identical state.
__device__ int    g_cnt[NN];
__device__ int    g_rptr[NN + 1];
__device__ int    g_bar;                // grid barrier counter (reset by scatter)
__device__ volatile int g_flag[NBLK];   // lookback flags (reset by gemm block 0)
__device__ volatile int g_aggr[NBLK];
__device__ volatile int g_incl[NBLK];
__device__ int    g_cols[EE];
__device__ float  g_dinv[NN];        // 1/sqrt(deg+1)
__device__ float  g_w[NN];           // 1/(deg+1)
__device__ float  g_sqd[NN];         // sqrt(deg+1)
__device__ float4 g_h32A[NN * 10];   // fp32 state (160 B/row)
__device__ float4 g_h32B[NN * 10];
__device__ uint4  g_h16A[NN * 6];    // fp16 gather copy (96 B/row, 80 B used)
__device__ uint4  g_h16B[NN * 6];

// ---------------- fused histogram + decoupled-lookback scan ----------------
__global__ void __launch_bounds__(1024, 1) histscan_kernel(const int4* __restrict__ row4) {
    int t = threadIdx.x, b = blockIdx.x;
    int gtid = b * 1024 + t;
    const int NTH = NBLK * 1024;

    for (int i = gtid; i < EE / 4; i += NTH) {
        int4 r = row4[i];
        atomicAdd(&g_cnt[r.x], 1);
        atomicAdd(&g_cnt[r.y], 1);
        atomicAdd(&g_cnt[r.z], 1);
        atomicAdd(&g_cnt[r.w], 1);
    }
    __syncthreads();
    if (t == 0) {
        __threadfence();
        atomicAdd(&g_bar, 1);
        while (*((volatile int*)&g_bar) < NBLK) { }
        __threadfence();
    }
    __syncthreads();

    __shared__ int wsum[32];
    __shared__ int chunk_prefix;
    int i = b * 1024 + t;
    int lane = t & 31, w = t >> 5;
    int v = (i < NN) ? g_cnt[i] : 0;
    int x = v;
    #pragma unroll
    for (int o = 1; o < 32; o <<= 1) {
        int y = __shfl_up_sync(0xffffffffu, x, o);
        if (lane >= o) x += y;
    }
    if (lane == 31) wsum[w] = x;
    __syncthreads();
    if (w == 0) {
        int s = wsum[lane];
        #pragma unroll
        for (int o = 1; o < 32; o <<= 1) {
            int y = __shfl_up_sync(0xffffffffu, s, o);
            if (lane >= o) s += y;
        }
        wsum[lane] = s;
    }
    __syncthreads();
    int incl = x + (w > 0 ? wsum[w - 1] : 0);

    if (t == 1023) {
        g_aggr[b] = incl;
        __threadfence();
        g_flag[b] = 1;
        int sum = 0;
        for (int p = b - 1; p >= 0; ) {
            int f;
            while ((f = g_flag[p]) == 0) { }
            if (f == 2) { sum += g_incl[p]; break; }
            sum += g_aggr[p];
            --p;
        }
        g_incl[b] = sum + incl;
        __threadfence();
        g_flag[b] = 2;
        chunk_prefix = sum;
        if (b == NBLK - 1) g_rptr[NN] = EE;
    }
    __syncthreads();
    int pre = chunk_prefix;
    if (i < NN) {
        g_rptr[i] = pre + incl - v;
        float df = (float)v + 1.0f;
        g_dinv[i] = rsqrtf(df);
        g_w[i]    = 1.0f / df;
        g_sqd[i]  = sqrtf(df);
    }
}

// ---------------- countdown scatter (restores g_cnt to 0; resets g_bar) -----
__global__ void scatter_kernel(const int4* __restrict__ row4, const int4* __restrict__ col4) {
    if (blockIdx.x == 0 && threadIdx.x == 0) g_bar = 0;   // replay determinism
    int i = blockIdx.x * blockDim.x + threadIdx.x;
    if (i < EE / 8) {
        int4 r0 = row4[2 * i], r1 = row4[2 * i + 1];
        int4 c0 = col4[2 * i], c1 = col4[2 * i + 1];
        int p;
        p = g_rptr[r0.x] + atomicAdd(&g_cnt[r0.x], -1) - 1; g_cols[p] = c0.x;
        p = g_rptr[r0.y] + atomicAdd(&g_cnt[r0.y], -1) - 1; g_cols[p] = c0.y;
        p = g_rptr[r0.z] + atomicAdd(&g_cnt[r0.z], -1) - 1; g_cols[p] = c0.z;
        p = g_rptr[r0.w] + atomicAdd(&g_cnt[r0.w], -1) - 1; g_cols[p] = c0.w;
        p = g_rptr[r1.x] + atomicAdd(&g_cnt[r1.x], -1) - 1; g_cols[p] = c1.x;
        p = g_rptr[r1.y] + atomicAdd(&g_cnt[r1.y], -1) - 1; g_cols[p] = c1.y;
        p = g_rptr[r1.z] + atomicAdd(&g_cnt[r1.z], -1) - 1; g_cols[p] = c1.z;
        p = g_rptr[r1.w] + atomicAdd(&g_cnt[r1.w], -1) - 1; g_cols[p] = c1.w;
    }
}

// ---------------- GEMM: s0 = dinv ⊙ (feat @ W^T), f32x2 k-pair accumulation --
// 1 node/thread, 40 classes as 40 f32x2 accumulators (k-even/k-odd split;
// one cross-add at the end). W pairs = ws4 float4 reinterpreted -> no dup,
// no transpose. fs stride 9 (conflict-free); ws reads warp-uniform broadcast.
#define GEMM_SMEM ((256 * 9 + 40 * 32) * 16)   // 57344 B
__global__ void __launch_bounds__(256, 2)
gemm_kernel(const float4* __restrict__ feat4,
            const float4* __restrict__ W4,
            float4* __restrict__ out32,
            uint4*  __restrict__ out16) {
    extern __shared__ float4 dynsm[];
    float4* fs4 = dynsm;              // 256 rows x 8 f4, stride 9 (per k-chunk)
    float4* ws4 = dynsm + 256 * 9;    // 40 x 32

    int t = threadIdx.x;
    int n0 = blockIdx.x * 256;
    int node = n0 + t;

    // reset lookback flags for the next graph replay
    if (blockIdx.x == 0 && t < NBLK) g_flag[t] = 0;

    for (int i = t; i < 40 * 32; i += 256) ws4[i] = W4[i];

    unsigned long long acc[40];
    #pragma unroll
    for (int c = 0; c < 40; c++) acc[c] = 0ull;

    for (int kc = 0; kc < 4; kc++) {
        __syncthreads();
        #pragma unroll
        for (int u = 0; u < 8; u++) {
            int i = u * 256 + t;
            int r = i >> 3, j = i & 7;
            float4 v = make_float4(0.f, 0.f, 0.f, 0.f);
            if (n0 + r < NN) v = feat4[(n0 + r) * 32 + kc * 8 + j];
            fs4[r * 9 + j] = v;
        }
        __syncthreads();
        #pragma unroll
        for (int j = 0; j < 8; j++) {
            ulonglong2 fq = *reinterpret_cast<const ulonglong2*>(&fs4[t * 9 + j]);
            #pragma unroll
            for (int c = 0; c < 40; c++) {
                ulonglong2 wq = *reinterpret_cast<const ulonglong2*>(&ws4[c * 32 + kc * 8 + j]);
                FMA2(acc[c], fq.x, wq.x);
                FMA2(acc[c], fq.y, wq.y);
            }
        }
    }

    if (node < NN) {
        float dv = g_dinv[node];
        float af[40];
        #pragma unroll
        for (int c = 0; c < 40; c++) {
            float lo = __uint_as_float((unsigned)acc[c]);
            float hi = __uint_as_float((unsigned)(acc[c] >> 32));
            af[c] = (lo + hi) * dv;
        }
        float4* op = out32 + node * 10;
        #pragma unroll
        for (int q = 0; q < 10; q++)
            op[q] = make_float4(af[4 * q], af[4 * q + 1], af[4 * q + 2], af[4 * q + 3]);
        uint4* hp = out16 + node * 6;
        #pragma unroll
        for (int q = 0; q < 5; q++) {
            uint4 hv;
            __half2* h2 = reinterpret_cast<__half2*>(&hv);
            h2[0] = __floats2half2_rn(af[8 * q],     af[8 * q + 1]);
            h2[1] = __floats2half2_rn(af[8 * q + 2], af[8 * q + 3]);
            h2[2] = __floats2half2_rn(af[8 * q + 4], af[8 * q + 5]);
            h2[3] = __floats2half2_rn(af[8 * q + 6], af[8 * q + 7]);
            hp[q] = hv;
        }
    }
}

// ---------------- propagation: s' = 0.5 s + 0.5 w (A s + s) -------------------
// fp16 HADD2 accumulation (issue-bound kernel: 4 HADD2/edge vs 16 cvt+add).
template <int LAST>
__global__ void spmm_kernel(const float4* __restrict__ h32in,
                            const uint4*  __restrict__ h16in,
                            float4* __restrict__ h32out,
                            uint4*  __restrict__ h16out,
                            const float4* __restrict__ bias4,
                            const float4* __restrict__ gamma4,
                            const float4* __restrict__ beta4,
                            float4* __restrict__ dout) {
    int lane = threadIdx.x & 31;
    int row  = blockIdx.x * 8 + (threadIdx.x >> 5);
    int sub  = lane / 5;              // 0..5 active edge groups; lanes 30,31 idle
    int fl   = lane - sub * 5;        // uint4 slot within the fp16 row

    int s = g_rptr[row], e = g_rptr[row + 1];
    int deg = e - s;

    // hoist self-row loads so they overlap the gathers
    float4 sA = make_float4(0.f, 0.f, 0.f, 0.f), sB = sA;
    if (lane < 5) {
        sA = h32in[row * 10 + 2 * fl];
        sB = h32in[row * 10 + 2 * fl + 1];
    }

    __half2 h0 = __float2half2_rn(0.f);
    __half2 acc2[4] = {h0, h0, h0, h0};

    if (deg <= 30) {
        // all col indices cached in one register; gather rounds independent
        int cReg = (lane < deg) ? __ldg(&g_cols[s + lane]) : 0;
        #pragma unroll
        for (int j = 0; j < 5; j++) {
            int src = j * 6 + sub;
            int c = __shfl_sync(0xffffffffu, cReg, src < 31 ? src : 0);
            bool p = (lane < 30) && (src < deg);
            if (p) {
                uint4 v = __ldcg(&h16in[c * 6 + fl]);
                const __half2* hv = reinterpret_cast<const __half2*>(&v);
                acc2[0] = __hadd2(acc2[0], hv[0]);
                acc2[1] = __hadd2(acc2[1], hv[1]);
                acc2[2] = __hadd2(acc2[2], hv[2]);
                acc2[3] = __hadd2(acc2[3], hv[3]);
            }
        }
    } else {
        #pragma unroll 2
        for (int i = s; i < e; i += 6) {
            bool p = (lane < 30) && (i + sub < e);
            if (p) {
                int c = __ldg(&g_cols[i + sub]);
                uint4 v = __ldcg(&h16in[c * 6 + fl]);
                const __half2* hv = reinterpret_cast<const __half2*>(&v);
                acc2[0] = __hadd2(acc2[0], hv[0]);
                acc2[1] = __hadd2(acc2[1], hv[1]);
                acc2[2] = __hadd2(acc2[2], hv[2]);
                acc2[3] = __hadd2(acc2[3], hv[3]);
            }
        }
    }
    // guarded 6-group combine in fp16 (see R4/R6 post-mortems for the shfl
    // self-return + lane-pollution hazards behind the guard pattern):
    //   off=15 (lane<15), off=10 (lane<5), off=5 (lane<5)
    {
        int tt;
        #define COMBH1(x, off, lim) \
            tt = __shfl_down_sync(0xffffffffu, *reinterpret_cast<int*>(&(x)), off); \
            if (lane < lim) (x) = __hadd2((x), *reinterpret_cast<__half2*>(&tt));
        #define COMBH(x) COMBH1(x, 15, 15) COMBH1(x, 10, 5) COMBH1(x, 5, 5)
        COMBH(acc2[0]) COMBH(acc2[1]) COMBH(acc2[2]) COMBH(acc2[3])
        #undef COMBH
        #undef COMBH1
    }

    float p1 = 0.f, p2 = 0.f;
    float4 rA, rB;
    if (lane < 5) {
        float2 f0 = __half22float2(acc2[0]);
        float2 f1 = __half22float2(acc2[1]);
        float2 f2 = __half22float2(acc2[2]);
        float2 f3 = __half22float2(acc2[3]);
        float4 accA = make_float4(f0.x, f0.y, f1.x, f1.y);
        float4 accB = make_float4(f2.x, f2.y, f3.x, f3.y);
        float wv = g_w[row];
        rA.x = 0.5f * sA.x + 0.5f * wv * (accA.x + sA.x);
        rA.y = 0.5f * sA.y + 0.5f * wv * (accA.y + sA.y);
        rA.z = 0.5f * sA.z + 0.5f * wv * (accA.z + sA.z);
        rA.w = 0.5f * sA.w + 0.5f * wv * (accA.w + sA.w);
        rB.x = 0.5f * sB.x + 0.5f * wv * (accB.x + sB.x);
        rB.y = 0.5f * sB.y + 0.5f * wv * (accB.y + sB.y);
        rB.z = 0.5f * sB.z + 0.5f * wv * (accB.z + sB.z);
        rB.w = 0.5f * sB.w + 0.5f * wv * (accB.w + sB.w);
        if (!LAST) {
            h32out[row * 10 + 2 * fl]     = rA;
            h32out[row * 10 + 2 * fl + 1] = rB;
            uint4 hv;
            __half2* hp = reinterpret_cast<__half2*>(&hv);
            hp[0] = __floats2half2_rn(rA.x, rA.y);
            hp[1] = __floats2half2_rn(rA.z, rA.w);
            hp[2] = __floats2half2_rn(rB.x, rB.y);
            hp[3] = __floats2half2_rn(rB.z, rB.w);
            h16out[row * 6 + fl] = hv;
        } else {
            float q = g_sqd[row];                 // unscale: h = s * sqrt(deg+1)
            float4 bA = bias4[2 * fl], bB = bias4[2 * fl + 1];
            rA.x = rA.x * q + bA.x;  rA.y = rA.y * q + bA.y;
            rA.z = rA.z * q + bA.z;  rA.w = rA.w * q + bA.w;
            rB.x = rB.x * q + bB.x;  rB.y = rB.y * q + bB.y;
            rB.z = rB.z * q + bB.z;  rB.w = rB.w * q + bB.w;
            p1 = rA.x + rA.y + rA.z + rA.w + rB.x + rB.y + rB.z + rB.w;
            p2 = rA.x * rA.x + rA.y * rA.y + rA.z * rA.z + rA.w * rA.w
               + rB.x * rB.x + rB.y * rB.y + rB.z * rB.z + rB.w * rB.w;
        }
    }
    if (LAST) {
        #pragma unroll
        for (int o = 16; o; o >>= 1) {
            p1 += __shfl_xor_sync(0xffffffffu, p1, o);
            p2 += __shfl_xor_sync(0xffffffffu, p2, o);
        }
        if (lane < 5) {
            float mu   = p1 * (1.0f / CC);
            float rstd = rsqrtf(p2 * (1.0f / CC) - mu * mu + LN_EPS);
            float4 gA = gamma4[2 * fl], gB = gamma4[2 * fl + 1];
            float4 eA = beta4[2 * fl],  eB = beta4[2 * fl + 1];
            float4 oA, oB;
            oA.x = (rA.x - mu) * rstd * gA.x + eA.x;
            oA.y = (rA.y - mu) * rstd * gA.y + eA.y;
            oA.z = (rA.z - mu) * rstd * gA.z + eA.z;
            oA.w = (rA.w - mu) * rstd * gA.w + eA.w;
            oB.x = (rB.x - mu) * rstd * gB.x + eB.x;
            oB.y = (rB.y - mu) * rstd * gB.y + eB.y;
            oB.z = (rB.z - mu) * rstd * gB.z + eB.z;
            oB.w = (rB.w - mu) * rstd * gB.w + eB.w;
            dout[row * 10 + 2 * fl]     = oA;
            dout[row * 10 + 2 * fl + 1] = oB;
        }
    }
}

// ---------------- launch ----------------
extern "C" void kernel_launch(void* const* d_in, const int* in_sizes, int n_in,
                              void* d_out, int out_size) {
    const float* feat  = (const float*)d_in[0];
    const int*   row   = (const int*)d_in[1];
    const int*   col   = (const int*)d_in[2];
    const float* W     = (const float*)d_in[3];
    const float* bias  = (const float*)d_in[4];
    const float* gamma = (const float*)d_in[5];
    const float* beta  = (const float*)d_in[6];

    void *pA32, *pB32, *pA16, *pB16;
    cudaGetSymbolAddress(&pA32, g_h32A);
    cudaGetSymbolAddress(&pB32, g_h32B);
    cudaGetSymbolAddress(&pA16, g_h16A);
    cudaGetSymbolAddress(&pB16, g_h16B);
    float4* A32 = (float4*)pA32;  float4* B32 = (float4*)pB32;
    uint4*  A16 = (uint4*)pA16;   uint4*  B16 = (uint4*)pB16;

    cudaFuncSetAttribute(gemm_kernel, cudaFuncAttributeMaxDynamicSharedMemorySize,
                         GEMM_SMEM);

    // launches: 1=histscan, 2=scatter, 3=gemm, 4=spmm1 (<- the profiled slot)
    histscan_kernel<<<NBLK, 1024>>>((const int4*)row);
    scatter_kernel<<<(EE / 8 + 255) / 256, 256>>>((const int4*)row, (const int4*)col);
    gemm_kernel<<<(NN + 255) / 256, 256, GEMM_SMEM>>>((const float4*)feat,
                                                      (const float4*)W, A32, A16);

    int sblocks = NN / 8;
    spmm_kernel<0><<<sblocks, 256>>>(A32, A16, B32, B16, nullptr, nullptr, nullptr, nullptr);
    spmm_kernel<0><<<sblocks, 256>>>(B32, B16, A32, A16, nullptr, nullptr, nullptr, nullptr);
    spmm_kernel<0><<<sblocks, 256>>>(A32, A16, B32, B16, nullptr, nullptr, nullptr, nullptr);
    spmm_kernel<1><<<sblocks, 256>>>(B32, B16, nullptr, nullptr,
                                     (const float4*)bias, (const float4*)gamma,
                                     (const float4*)beta, (float4*)d_out);
}

// round 14
// speedup vs baseline: 1.5240x; 1.5240x over previous
#include <cuda_runtime.h>
#include <cuda_fp16.h>

#define NN 100000
#define EE 1600000
#define CC 40
#define NBLK 98          // ceil(NN/1024)
#define LN_EPS 1e-5f

// ---------------- device scratch ----------------
// g_cnt: zero at process start; histscan builds degree; countdown scatter
// restores it to exactly 0 -> every graph replay sees identical state.
__device__ int    g_cnt[NN];
__device__ int    g_rptr[NN + 1];
__device__ int    g_bar;                // grid barrier counter (reset by scatter)
__device__ volatile int g_flag[NBLK];   // lookback flags (reset by gemm block 0)
__device__ volatile int g_aggr[NBLK];
__device__ volatile int g_incl[NBLK];
__device__ int    g_cols[EE];
__device__ float  g_dinv[NN];        // 1/sqrt(deg+1)
__device__ float  g_w[NN];           // 1/(deg+1)
__device__ float  g_sqd[NN];         // sqrt(deg+1)
__device__ float4 g_bufA[NN * 10];   // fp32 state ping-pong (160 B/row)
__device__ float4 g_bufB[NN * 10];

// ---------------- fused histogram + decoupled-lookback scan ----------------
// 98 blocks x 1024 threads, all resident -> DIY grid barrier is deadlock-free.
__global__ void __launch_bounds__(1024, 1) histscan_kernel(const int4* __restrict__ row4) {
    int t = threadIdx.x, b = blockIdx.x;
    int gtid = b * 1024 + t;
    const int NTH = NBLK * 1024;

    for (int i = gtid; i < EE / 4; i += NTH) {
        int4 r = row4[i];
        atomicAdd(&g_cnt[r.x], 1);
        atomicAdd(&g_cnt[r.y], 1);
        atomicAdd(&g_cnt[r.z], 1);
        atomicAdd(&g_cnt[r.w], 1);
    }
    __syncthreads();
    if (t == 0) {
        __threadfence();
        atomicAdd(&g_bar, 1);
        while (*((volatile int*)&g_bar) < NBLK) { }
        __threadfence();
    }
    __syncthreads();

    __shared__ int wsum[32];
    __shared__ int chunk_prefix;
    int i = b * 1024 + t;
    int lane = t & 31, w = t >> 5;
    int v = (i < NN) ? g_cnt[i] : 0;
    int x = v;
    #pragma unroll
    for (int o = 1; o < 32; o <<= 1) {
        int y = __shfl_up_sync(0xffffffffu, x, o);
        if (lane >= o) x += y;
    }
    if (lane == 31) wsum[w] = x;
    __syncthreads();
    if (w == 0) {
        int s = wsum[lane];
        #pragma unroll
        for (int o = 1; o < 32; o <<= 1) {
            int y = __shfl_up_sync(0xffffffffu, s, o);
            if (lane >= o) s += y;
        }
        wsum[lane] = s;
    }
    __syncthreads();
    int incl = x + (w > 0 ? wsum[w - 1] : 0);

    if (t == 1023) {
        g_aggr[b] = incl;
        __threadfence();
        g_flag[b] = 1;
        int sum = 0;
        for (int p = b - 1; p >= 0; ) {
            int f;
            while ((f = g_flag[p]) == 0) { }
            if (f == 2) { sum += g_incl[p]; break; }
            sum += g_aggr[p];
            --p;
        }
        g_incl[b] = sum + incl;
        __threadfence();
        g_flag[b] = 2;
        chunk_prefix = sum;
        if (b == NBLK - 1) g_rptr[NN] = EE;
    }
    __syncthreads();
    int pre = chunk_prefix;
    if (i < NN) {
        g_rptr[i] = pre + incl - v;
        float df = (float)v + 1.0f;
        g_dinv[i] = rsqrtf(df);
        g_w[i]    = 1.0f / df;
        g_sqd[i]  = sqrtf(df);
    }
}

// ---------------- countdown scatter (restores g_cnt to 0; resets g_bar) -----
__global__ void scatter_kernel(const int4* __restrict__ row4, const int4* __restrict__ col4) {
    if (blockIdx.x == 0 && threadIdx.x == 0) g_bar = 0;   // replay determinism
    int i = blockIdx.x * blockDim.x + threadIdx.x;
    if (i < EE / 8) {
        int4 r0 = row4[2 * i], r1 = row4[2 * i + 1];
        int4 c0 = col4[2 * i], c1 = col4[2 * i + 1];
        int p;
        p = g_rptr[r0.x] + atomicAdd(&g_cnt[r0.x], -1) - 1; g_cols[p] = c0.x;
        p = g_rptr[r0.y] + atomicAdd(&g_cnt[r0.y], -1) - 1; g_cols[p] = c0.y;
        p = g_rptr[r0.z] + atomicAdd(&g_cnt[r0.z], -1) - 1; g_cols[p] = c0.z;
        p = g_rptr[r0.w] + atomicAdd(&g_cnt[r0.w], -1) - 1; g_cols[p] = c0.w;
        p = g_rptr[r1.x] + atomicAdd(&g_cnt[r1.x], -1) - 1; g_cols[p] = c1.x;
        p = g_rptr[r1.y] + atomicAdd(&g_cnt[r1.y], -1) - 1; g_cols[p] = c1.y;
        p = g_rptr[r1.z] + atomicAdd(&g_cnt[r1.z], -1) - 1; g_cols[p] = c1.z;
        p = g_rptr[r1.w] + atomicAdd(&g_cnt[r1.w], -1) - 1; g_cols[p] = c1.w;
    }
}

// ---------------- GEMM: s0 = dinv ⊙ (feat @ W^T) ---------------------------
// 1 node/thread, 40 scalar-fmaf accumulators. fs: per-thread row (stride 9,
// conflict-free); ws: warp-uniform broadcast (1-phase). k chunked 4x32.
#define GEMM_SMEM ((256 * 9 + 40 * 32) * 16)   // 57344 B
__global__ void __launch_bounds__(256, 3)
gemm_kernel(const float4* __restrict__ feat4,
            const float4* __restrict__ W4,
            float4* __restrict__ out32) {
    extern __shared__ float4 dynsm[];
    float4* fs4 = dynsm;              // 256 rows x 8 f4, stride 9 (per k-chunk)
    float4* ws4 = dynsm + 256 * 9;    // 40 x 32

    int t = threadIdx.x;
    int n0 = blockIdx.x * 256;
    int node = n0 + t;

    // reset lookback flags for the next graph replay
    if (blockIdx.x == 0 && t < NBLK) g_flag[t] = 0;

    for (int i = t; i < 40 * 32; i += 256) ws4[i] = W4[i];

    float acc[40];
    #pragma unroll
    for (int c = 0; c < 40; c++) acc[c] = 0.f;

    for (int kc = 0; kc < 4; kc++) {
        __syncthreads();
        #pragma unroll
        for (int u = 0; u < 8; u++) {
            int i = u * 256 + t;
            int r = i >> 3, j = i & 7;
            float4 v = make_float4(0.f, 0.f, 0.f, 0.f);
            if (n0 + r < NN) v = feat4[(n0 + r) * 32 + kc * 8 + j];
            fs4[r * 9 + j] = v;
        }
        __syncthreads();
        #pragma unroll 2
        for (int j = 0; j < 8; j++) {
            float4 f = fs4[t * 9 + j];
            const float4* wp = &ws4[kc * 8 + j];
            #pragma unroll
            for (int c = 0; c < 40; c++) {
                float4 wv = wp[c * 32];            // warp-uniform -> broadcast
                acc[c] = fmaf(f.x, wv.x, acc[c]);
                acc[c] = fmaf(f.y, wv.y, acc[c]);
                acc[c] = fmaf(f.z, wv.z, acc[c]);
                acc[c] = fmaf(f.w, wv.w, acc[c]);
            }
        }
    }

    if (node < NN) {
        float dv = g_dinv[node];
        #pragma unroll
        for (int c = 0; c < 40; c++) acc[c] *= dv;
        float4* op = out32 + node * 10;
        #pragma unroll
        for (int q = 0; q < 10; q++)
            op[q] = make_float4(acc[4 * q], acc[4 * q + 1], acc[4 * q + 2], acc[4 * q + 3]);
    }
}

// ---------------- propagation: s' = 0.5 s + 0.5 w (A s + s) -------------------
// R2-proven layout: warp/row, 3 edge-groups x 10 lanes, fp32 float4 gathers
// (L1-cached: 16 MB state fits aggregate L1). LAST fuses unscale+bias+LN.
template <int LAST>
__global__ void spmm_kernel(const float4* __restrict__ hin,
                            float4* __restrict__ hout,
                            const float4* __restrict__ bias4,
                            const float4* __restrict__ gamma4,
                            const float4* __restrict__ beta4,
                            float4* __restrict__ dout) {
    int lane = threadIdx.x & 31;
    int row  = blockIdx.x * 8 + (threadIdx.x >> 5);
    int sub  = lane / 10;             // 0,1,2 active; lanes 30,31 idle
    int fl   = lane - sub * 10;       // 0..9 -> float4 slot in row

    int s = g_rptr[row], e = g_rptr[row + 1];

    // hoist self-row load so it overlaps the gathers
    float4 sr = make_float4(0.f, 0.f, 0.f, 0.f);
    if (lane < 10) sr = hin[row * 10 + lane];

    float4 acc = make_float4(0.f, 0.f, 0.f, 0.f);
    #pragma unroll 2
    for (int i = s; i < e; i += 3) {
        int ei = i + sub;
        bool p = (sub < 3) && (ei < e);
        if (p) {
            int c = __ldg(&g_cols[ei]);           // 10 lanes share -> broadcast
            float4 v = hin[c * 10 + fl];          // L1-cached gather
            acc.x += v.x; acc.y += v.y; acc.z += v.z; acc.w += v.w;
        }
    }
    // combine 3 edge-groups into lanes 0..9: read both sources BEFORE adding
    // (hazard-free; consuming lanes 0..9 read pure lanes 10..19 / 20..29)
    float4 b1, b2;
    b1.x = __shfl_down_sync(0xffffffffu, acc.x, 10);
    b1.y = __shfl_down_sync(0xffffffffu, acc.y, 10);
    b1.z = __shfl_down_sync(0xffffffffu, acc.z, 10);
    b1.w = __shfl_down_sync(0xffffffffu, acc.w, 10);
    b2.x = __shfl_down_sync(0xffffffffu, acc.x, 20);
    b2.y = __shfl_down_sync(0xffffffffu, acc.y, 20);
    b2.z = __shfl_down_sync(0xffffffffu, acc.z, 20);
    b2.w = __shfl_down_sync(0xffffffffu, acc.w, 20);
    acc.x += b1.x + b2.x; acc.y += b1.y + b2.y;
    acc.z += b1.z + b2.z; acc.w += b1.w + b2.w;

    float p1 = 0.f, p2 = 0.f;
    float4 r;
    if (lane < 10) {
        float wv = g_w[row];
        float sc = 0.5f + 0.5f * wv;              // residual + self-loop
        r.x = sr.x * sc + 0.5f * wv * acc.x;
        r.y = sr.y * sc + 0.5f * wv * acc.y;
        r.z = sr.z * sc + 0.5f * wv * acc.z;
        r.w = sr.w * sc + 0.5f * wv * acc.w;
        if (!LAST) {
            hout[row * 10 + lane] = r;
        } else {
            float q = g_sqd[row];                 // unscale: h = s * sqrt(deg+1)
            float4 bb = bias4[lane];
            r.x = r.x * q + bb.x;
            r.y = r.y * q + bb.y;
            r.z = r.z * q + bb.z;
            r.w = r.w * q + bb.w;
            p1 = r.x + r.y + r.z + r.w;
            p2 = r.x * r.x + r.y * r.y + r.z * r.z + r.w * r.w;
        }
    }
    if (LAST) {
        #pragma unroll
        for (int o = 16; o; o >>= 1) {
            p1 += __shfl_xor_sync(0xffffffffu, p1, o);
            p2 += __shfl_xor_sync(0xffffffffu, p2, o);
        }
        if (lane < 10) {
            float mu   = p1 * (1.0f / CC);
            float rstd = rsqrtf(p2 * (1.0f / CC) - mu * mu + LN_EPS);
            float4 g = gamma4[lane], be = beta4[lane];
            float4 o;
            o.x = (r.x - mu) * rstd * g.x + be.x;
            o.y = (r.y - mu) * rstd * g.y + be.y;
            o.z = (r.z - mu) * rstd * g.z + be.z;
            o.w = (r.w - mu) * rstd * g.w + be.w;
            dout[row * 10 + lane] = o;
        }
    }
}

// ---------------- launch ----------------
extern "C" void kernel_launch(void* const* d_in, const int* in_sizes, int n_in,
                              void* d_out, int out_size) {
    const float* feat  = (const float*)d_in[0];
    const int*   row   = (const int*)d_in[1];
    const int*   col   = (const int*)d_in[2];
    const float* W     = (const float*)d_in[3];
    const float* bias  = (const float*)d_in[4];
    const float* gamma = (const float*)d_in[5];
    const float* beta  = (const float*)d_in[6];

    void *pA, *pB;
    cudaGetSymbolAddress(&pA, g_bufA);
    cudaGetSymbolAddress(&pB, g_bufB);
    float4* A = (float4*)pA;
    float4* B = (float4*)pB;

    cudaFuncSetAttribute(gemm_kernel, cudaFuncAttributeMaxDynamicSharedMemorySize,
                         GEMM_SMEM);

    // launches: 1=histscan, 2=scatter, 3=gemm, 4=spmm1 (<- the profiled slot)
    histscan_kernel<<<NBLK, 1024>>>((const int4*)row);
    scatter_kernel<<<(EE / 8 + 255) / 256, 256>>>((const int4*)row, (const int4*)col);
    gemm_kernel<<<(NN + 255) / 256, 256, GEMM_SMEM>>>((const float4*)feat,
                                                      (const float4*)W, A);

    int sblocks = NN / 8;
    spmm_kernel<0><<<sblocks, 256>>>(A, B, nullptr, nullptr, nullptr, nullptr);
    spmm_kernel<0><<<sblocks, 256>>>(B, A, nullptr, nullptr, nullptr, nullptr);
    spmm_kernel<0><<<sblocks, 256>>>(A, B, nullptr, nullptr, nullptr, nullptr);
    spmm_kernel<1><<<sblocks, 256>>>(B, A,
                                     (const float4*)bias, (const float4*)gamma,
                                     (const float4*)beta, (float4*)d_out);
}